// round 1
// baseline (speedup 1.0000x reference)
#include <cuda_runtime.h>

#define Bn 8
#define Cn 12
#define Hn 384
#define Wn 384
#define HWc (Hn*Wn)
#define BHWc (Bn*HWc)
#define LAMf 0.05f
#define EPSf 1e-12f
#define INVN (1.0f/147456.0f)
#define SQ3H 0.86602540378443864676f
#define TWO_PI_D 6.283185307179586476925286766559

// ---------------- scratch (static device allocations; allowed) ----------------
__device__ float2 g_Y[(size_t)Bn*Cn*HWc];   // coil k-space / intermediate, 113 MB
__device__ float2 g_p[BHWc];                // CG search direction (and Aop input)
__device__ float2 g_r[BHWc];                // residual
__device__ float2 g_Ap[BHWc];               // Aop(p)
__device__ float  g_rd[Bn], g_rdnew[Bn], g_pAp[Bn];
__device__ float2 g_T[384];                 // e^{-2*pi*i*j/384}

// ---------------- complex helpers ----------------
__device__ __forceinline__ float2 cmul(float2 a, float2 b){
    return make_float2(fmaf(a.x,b.x,-a.y*b.y), fmaf(a.x,b.y, a.y*b.x));
}
__device__ __forceinline__ float2 cadd(float2 a, float2 b){ return make_float2(a.x+b.x, a.y+b.y); }
__device__ __forceinline__ float2 csub(float2 a, float2 b){ return make_float2(a.x-b.x, a.y-b.y); }

template<bool INV>
__device__ __forceinline__ float2 twid(int j){
    float2 w = g_T[j];                 // (cos, -sin)
    return INV ? make_float2(w.x, -w.y) : w;
}

// ---------------- Stockham stages 1..6 (stage 0 is fused with input load) ----------------
// 192-thread version: 3 sub-FFTs x 64 butterflies, contiguous layout [384]
template<bool INV>
__device__ __forceinline__ float2* stages192(float2* X, float2* Y, int sub, int u){
    const int base = sub*128;
    #pragma unroll
    for (int st = 1; st < 7; st++){
        int q  = u & ((1<<st)-1);
        int p  = u >> st;
        int i0 = base + q + (p<<st);
        float2 a = X[i0];
        float2 b = X[i0+64];
        float2 w = twid<INV>(p*(3<<st));
        int o0 = base + q + (p<<(st+1));
        Y[o0]          = cadd(a,b);
        Y[o0+(1<<st)]  = cmul(csub(a,b), w);
        float2* t = X; X = Y; Y = t;
        __syncthreads();
    }
    return X;
}

// 512-thread version: 8 columns, layout [idx*8+col]
template<bool INV>
__device__ __forceinline__ float2* stages512(float2* X, float2* Y, int tid){
    #pragma unroll
    for (int st = 1; st < 7; st++){
        #pragma unroll
        for (int k = 0; k < 3; k++){
            int w   = tid + k*512;        // 1536 butterflies per stage
            int col = w & 7;
            int t   = w >> 3;
            int sub = t >> 6, u = t & 63;
            int base = sub*128;
            int q  = u & ((1<<st)-1);
            int p  = u >> st;
            int i0 = base + q + (p<<st);
            float2 a = X[i0*8+col];
            float2 b = X[(i0+64)*8+col];
            float2 tw = twid<INV>(p*(3<<st));
            int o0 = base + q + (p<<(st+1));
            Y[o0*8+col]            = cadd(a,b);
            Y[(o0+(1<<st))*8+col]  = cmul(csub(a,b), tw);
        }
        float2* tp = X; X = Y; Y = tp;
        __syncthreads();
    }
    return X;
}

// ---------------- init: rhs = adj + lam*x ; x0 = rhs ; p = rhs ; twiddles; zero scalars --------
__global__ void k_init(const float2* __restrict__ x, const float2* __restrict__ adj, float2* __restrict__ xout){
    int idx = blockIdx.y*HWc + blockIdx.x*256 + threadIdx.x;
    float2 xv = x[idx], av = adj[idx];
    float2 rhs = make_float2(fmaf(LAMf, xv.x, av.x), fmaf(LAMf, xv.y, av.y));
    xout[idx] = rhs;
    g_p[idx]  = rhs;
    if (blockIdx.x == 0 && blockIdx.y == 0){
        if (threadIdx.x < Bn){ g_rd[threadIdx.x]=0.f; g_rdnew[threadIdx.x]=0.f; g_pAp[threadIdx.x]=0.f; }
        for (int j = threadIdx.x; j < 384; j += 256){
            double s, c;
            sincos(TWO_PI_D * (double)j / 384.0, &s, &c);
            g_T[j] = make_float2((float)c, (float)(-s));
        }
    }
}

// ---------------- K1: per (b,row): forward row FFT of m_c * p, all 12 coils ----------------
__global__ void __launch_bounds__(192) k_fwd_rows(const float2* __restrict__ maps){
    __shared__ float2 V[384], M[384], A[384], Bb[384];
    const int tid = threadIdx.x;
    const int row = blockIdx.x, b = blockIdx.y;
    const int sub = tid >> 6, u = tid & 63;

    for (int j = tid; j < 384; j += 192) V[j] = g_p[(b*Hn + row)*Wn + j];
    __syncthreads();

    for (int c = 0; c < Cn; c++){
        const float2* mr = maps + (size_t)(((b*Cn + c)*Hn) + row)*Wn;
        for (int j = tid; j < 384; j += 192) M[j] = __ldg(&mr[j]);
        __syncthreads();
        // stage 0: read natural (decimated by 3), fused coil multiply
        {
            int n0 = sub + 3*u;
            float2 a  = cmul(M[n0],     V[n0]);
            float2 b2 = cmul(M[n0+192], V[n0+192]);
            float2 w  = twid<false>(3*u);
            int o = sub*128 + 2*u;
            A[o]   = cadd(a,b2);
            A[o+1] = cmul(csub(a,b2), w);
        }
        __syncthreads();
        float2* F = stages192<false>(A, Bb, sub, u);
        // radix-3 combine, natural order -> global
        if (tid < 128){
            int k2 = tid;
            float2 t0 = F[k2];
            float2 t1 = cmul(F[128+k2], twid<false>(k2));
            float2 t2 = cmul(F[256+k2], twid<false>(2*k2));
            float2 su = cadd(t1,t2), dv = csub(t1,t2);
            float ex = t0.x - 0.5f*su.x, ey = t0.y - 0.5f*su.y;
            float2* yo = g_Y + (size_t)(((b*Cn + c)*Hn) + row)*Wn;
            yo[k2]      = cadd(t0, su);
            yo[128+k2]  = make_float2(ex + SQ3H*dv.y, ey - SQ3H*dv.x);
            yo[256+k2]  = make_float2(ex - SQ3H*dv.y, ey + SQ3H*dv.x);
        }
        // next iteration's M-load + barrier orders combine(read A) before stage0(write A)
    }
}

// ---------------- K2: per (b,c,8-col tile): col FFT -> mask*1/N -> col IFFT ----------------
__global__ void __launch_bounds__(512) k_colpass(const float* __restrict__ mask){
    __shared__ float2 A[3072], Bb[3072];   // 48 KB exactly
    const int tid  = threadIdx.x;
    const int ct   = blockIdx.x, c = blockIdx.y, b = blockIdx.z;
    const int col0 = ct*8;
    const size_t base = (size_t)((b*Cn + c))*HWc;

    for (int j = tid; j < 3072; j += 512){
        int col = j & 7, h = j >> 3;
        A[j] = g_Y[base + (size_t)h*Wn + col0 + col];
    }
    __syncthreads();

    // forward stage 0 (natural decimated read)
    #pragma unroll
    for (int k = 0; k < 3; k++){
        int w = tid + k*512;
        int col = w & 7; int t = w >> 3;
        int sub = t >> 6, u = t & 63;
        int n0 = sub + 3*u;
        float2 a  = A[n0*8+col];
        float2 b2 = A[(n0+192)*8+col];
        float2 tw = twid<false>(3*u);
        int o = (sub*128 + 2*u)*8 + col;
        Bb[o]   = cadd(a,b2);
        Bb[o+8] = cmul(csub(a,b2), tw);
    }
    __syncthreads();
    float2* F = stages512<false>(Bb, A, tid);   // returns Bb

    // forward combine -> natural into A, fused with mask * 1/N
    #pragma unroll
    for (int k = 0; k < 2; k++){
        int w = tid + k*512;                    // 1024 (k2,col) groups
        int col = w & 7, k2 = w >> 3;
        float2 t0 = F[k2*8+col];
        float2 t1 = cmul(F[(128+k2)*8+col], twid<false>(k2));
        float2 t2 = cmul(F[(256+k2)*8+col], twid<false>(2*k2));
        float2 su = cadd(t1,t2), dv = csub(t1,t2);
        float ex = t0.x - 0.5f*su.x, ey = t0.y - 0.5f*su.y;
        const float* mb = mask + b*HWc + col0 + col;
        float s0 = __ldg(&mb[(size_t)k2*Wn])        * INVN;
        float s1 = __ldg(&mb[(size_t)(128+k2)*Wn])  * INVN;
        float s2 = __ldg(&mb[(size_t)(256+k2)*Wn])  * INVN;
        float2 r0 = cadd(t0, su);
        float2 r1 = make_float2(ex + SQ3H*dv.y, ey - SQ3H*dv.x);
        float2 r2 = make_float2(ex - SQ3H*dv.y, ey + SQ3H*dv.x);
        A[k2*8+col]        = make_float2(r0.x*s0, r0.y*s0);
        A[(128+k2)*8+col]  = make_float2(r1.x*s1, r1.y*s1);
        A[(256+k2)*8+col]  = make_float2(r2.x*s2, r2.y*s2);
    }
    __syncthreads();

    // inverse stage 0
    #pragma unroll
    for (int k = 0; k < 3; k++){
        int w = tid + k*512;
        int col = w & 7; int t = w >> 3;
        int sub = t >> 6, u = t & 63;
        int n0 = sub + 3*u;
        float2 a  = A[n0*8+col];
        float2 b2 = A[(n0+192)*8+col];
        float2 tw = twid<true>(3*u);
        int o = (sub*128 + 2*u)*8 + col;
        Bb[o]   = cadd(a,b2);
        Bb[o+8] = cmul(csub(a,b2), tw);
    }
    __syncthreads();
    F = stages512<true>(Bb, A, tid);            // returns Bb

    // inverse combine -> global (natural order)
    #pragma unroll
    for (int k = 0; k < 2; k++){
        int w = tid + k*512;
        int col = w & 7, k2 = w >> 3;
        float2 t0 = F[k2*8+col];
        float2 t1 = cmul(F[(128+k2)*8+col], twid<true>(k2));
        float2 t2 = cmul(F[(256+k2)*8+col], twid<true>(2*k2));
        float2 su = cadd(t1,t2), dv = csub(t1,t2);
        float ex = t0.x - 0.5f*su.x, ey = t0.y - 0.5f*su.y;
        g_Y[base + (size_t)k2*Wn + col0 + col]        = cadd(t0, su);
        g_Y[base + (size_t)(128+k2)*Wn + col0 + col]  = make_float2(ex - SQ3H*dv.y, ey + SQ3H*dv.x);
        g_Y[base + (size_t)(256+k2)*Wn + col0 + col]  = make_float2(ex + SQ3H*dv.y, ey - SQ3H*dv.x);
    }
}

// ---------------- K3: per (b,row): inverse row FFT, conj(maps) combine, +lam*p, <p,Ap> -------
__global__ void __launch_bounds__(192) k_inv_rows(const float2* __restrict__ maps){
    __shared__ float2 Z[384], A[384], Bb[384], ACC[384];
    __shared__ float red[6];
    const int tid = threadIdx.x;
    const int row = blockIdx.x, b = blockIdx.y;
    const int sub = tid >> 6, u = tid & 63;

    for (int j = tid; j < 384; j += 192) ACC[j] = make_float2(0.f, 0.f);

    for (int c = 0; c < Cn; c++){
        const size_t rbase = (size_t)(((b*Cn + c)*Hn) + row)*Wn;
        for (int j = tid; j < 384; j += 192) Z[j] = g_Y[rbase + j];
        __syncthreads();
        // inverse stage 0
        {
            int n0 = sub + 3*u;
            float2 a  = Z[n0];
            float2 b2 = Z[n0+192];
            float2 w  = twid<true>(3*u);
            int o = sub*128 + 2*u;
            A[o]   = cadd(a,b2);
            A[o+1] = cmul(csub(a,b2), w);
        }
        __syncthreads();
        float2* F = stages192<true>(A, Bb, sub, u);
        if (tid < 128){
            int k2 = tid;
            float2 t0 = F[k2];
            float2 t1 = cmul(F[128+k2], twid<true>(k2));
            float2 t2 = cmul(F[256+k2], twid<true>(2*k2));
            float2 su = cadd(t1,t2), dv = csub(t1,t2);
            float ex = t0.x - 0.5f*su.x, ey = t0.y - 0.5f*su.y;
            float2 z0 = cadd(t0, su);
            float2 z1 = make_float2(ex - SQ3H*dv.y, ey + SQ3H*dv.x);
            float2 z2 = make_float2(ex + SQ3H*dv.y, ey - SQ3H*dv.x);
            const float2* mr = maps + (size_t)(((b*Cn + c)*Hn) + row)*Wn;
            float2 m0 = __ldg(&mr[k2]), m1 = __ldg(&mr[128+k2]), m2 = __ldg(&mr[256+k2]);
            // acc += conj(m) * z
            float2 a0 = ACC[k2];
            ACC[k2] = make_float2(fmaf(m0.x,z0.x, fmaf(m0.y,z0.y, a0.x)),
                                  fmaf(m0.x,z0.y, fmaf(-m0.y,z0.x, a0.y)));
            float2 a1 = ACC[128+k2];
            ACC[128+k2] = make_float2(fmaf(m1.x,z1.x, fmaf(m1.y,z1.y, a1.x)),
                                      fmaf(m1.x,z1.y, fmaf(-m1.y,z1.x, a1.y)));
            float2 a2 = ACC[256+k2];
            ACC[256+k2] = make_float2(fmaf(m2.x,z2.x, fmaf(m2.y,z2.y, a2.x)),
                                      fmaf(m2.x,z2.y, fmaf(-m2.y,z2.x, a2.y)));
        }
        __syncthreads();
    }

    // Ap = acc + lam*p ; accumulate Re<p,Ap> per batch
    float part = 0.f;
    #pragma unroll
    for (int k0 = 0; k0 < 2; k0++){
        int k = tid + k0*192;
        int gidx = (b*Hn + row)*Wn + k;
        float2 pv = g_p[gidx];
        float2 o = make_float2(fmaf(LAMf, pv.x, ACC[k].x), fmaf(LAMf, pv.y, ACC[k].y));
        g_Ap[gidx] = o;
        part = fmaf(pv.x, o.x, part);
        part = fmaf(pv.y, o.y, part);
    }
    #pragma unroll
    for (int off = 16; off > 0; off >>= 1) part += __shfl_down_sync(0xffffffffu, part, off);
    if ((tid & 31) == 0) red[tid >> 5] = part;
    __syncthreads();
    if (tid == 0){
        float s = 0.f;
        #pragma unroll
        for (int i = 0; i < 6; i++) s += red[i];
        atomicAdd(&g_pAp[b], s);
    }
}

// ---------------- r0: r = rhs - Aop(rhs); p = r; rd = <r,r> ----------------
__global__ void k_r0(const float2* __restrict__ xrhs){
    __shared__ float red[8];
    int b = blockIdx.y;
    int idx = b*HWc + blockIdx.x*256 + threadIdx.x;
    float2 rv = csub(xrhs[idx], g_Ap[idx]);
    g_r[idx] = rv;
    g_p[idx] = rv;
    float part = fmaf(rv.x, rv.x, rv.y*rv.y);
    #pragma unroll
    for (int off = 16; off > 0; off >>= 1) part += __shfl_down_sync(0xffffffffu, part, off);
    if ((threadIdx.x & 31) == 0) red[threadIdx.x >> 5] = part;
    __syncthreads();
    if (threadIdx.x == 0){
        float s = 0.f;
        #pragma unroll
        for (int i = 0; i < 8; i++) s += red[i];
        atomicAdd(&g_rd[b], s);
    }
}

// ---------------- CG updates ----------------
__global__ void k_upd1(float2* __restrict__ x){
    __shared__ float red[8];
    int b = blockIdx.y;
    int idx = b*HWc + blockIdx.x*256 + threadIdx.x;
    float alpha = g_rd[b] / (g_pAp[b] + EPSf);
    float2 pv = g_p[idx];
    float2 xv = x[idx];
    x[idx] = make_float2(fmaf(alpha, pv.x, xv.x), fmaf(alpha, pv.y, xv.y));
    float2 rv = g_r[idx];
    float2 ap = g_Ap[idx];
    rv = make_float2(fmaf(-alpha, ap.x, rv.x), fmaf(-alpha, ap.y, rv.y));
    g_r[idx] = rv;
    float part = fmaf(rv.x, rv.x, rv.y*rv.y);
    #pragma unroll
    for (int off = 16; off > 0; off >>= 1) part += __shfl_down_sync(0xffffffffu, part, off);
    if ((threadIdx.x & 31) == 0) red[threadIdx.x >> 5] = part;
    __syncthreads();
    if (threadIdx.x == 0){
        float s = 0.f;
        #pragma unroll
        for (int i = 0; i < 8; i++) s += red[i];
        atomicAdd(&g_rdnew[b], s);
    }
}

__global__ void k_upd2(){
    int b = blockIdx.y;
    int idx = b*HWc + blockIdx.x*256 + threadIdx.x;
    float beta = g_rdnew[b] / (g_rd[b] + EPSf);
    float2 rv = g_r[idx];
    float2 pv = g_p[idx];
    g_p[idx] = make_float2(fmaf(beta, pv.x, rv.x), fmaf(beta, pv.y, rv.y));
}

__global__ void k_scal(){ if (threadIdx.x < Bn) g_rd[threadIdx.x] = g_rdnew[threadIdx.x]; }
__global__ void k_zero(){ if (threadIdx.x < Bn){ g_pAp[threadIdx.x] = 0.f; g_rdnew[threadIdx.x] = 0.f; } }

// ---------------- launch ----------------
extern "C" void kernel_launch(void* const* d_in, const int* in_sizes, int n_in,
                              void* d_out, int out_size){
    const float2* x    = (const float2*)d_in[0];
    const float2* adj  = (const float2*)d_in[1];
    const float2* maps = (const float2*)d_in[2];
    const float*  mask = (const float*)d_in[3];
    float2* xout = (float2*)d_out;

    dim3 gElem(HWc/256, Bn);          // 576 x 8, 256 threads
    dim3 gRow(Hn, Bn);                // 384 x 8, 192 threads
    dim3 gCol(Wn/8, Cn, Bn);          // 48 x 12 x 8, 512 threads

    k_init<<<gElem, 256>>>(x, adj, xout);

    // r = rhs - Aop(rhs)  (g_p holds rhs)
    k_fwd_rows<<<gRow, 192>>>(maps);
    k_colpass<<<gCol, 512>>>(mask);
    k_inv_rows<<<gRow, 192>>>(maps);
    k_r0<<<gElem, 256>>>(xout);

    for (int it = 0; it < 10; ++it){
        k_zero<<<1, 32>>>();
        k_fwd_rows<<<gRow, 192>>>(maps);
        k_colpass<<<gCol, 512>>>(mask);
        k_inv_rows<<<gRow, 192>>>(maps);
        k_upd1<<<gElem, 256>>>(xout);
        k_upd2<<<gElem, 256>>>();
        k_scal<<<1, 32>>>();
    }
}